// round 4
// baseline (speedup 1.0000x reference)
#include <cuda_runtime.h>
#include <math.h>

// ---------------------------------------------------------------------------
// Revisit_RDLoss: debiased Sinkhorn divergence over softmax rows, 3 pairs.
//
// Stage 1 (gram_kernel): for each pair, Z = [exp(teacher_rows); exp(rec_rows)]
//   (32 rows x M). Accumulate G = Z Z^T (upper triangle, fp32 partials ->
//   fp64 atomics) and row sums S (fp64). Softmax normalization factors out:
//     dot(x_i, y_j) = G[i][16+j] / (S_i * S_{16+j}),   ||x_i||^2 = G[i][i]/S_i^2
// Stage 2 (solver_kernel): per pair, build C matrices (fp64 -> fp32) and run
//   the 60-step eps-scaled Sinkhorn scan + final extrapolation using the
//   exact reformulation  softmin_i = -eps * log1p( mean_j expm1((h_j-C_ij)/eps) )
//   (logw = -log B cancels analytically; all quantities stay ~1e-6, so fp32
//   expm1/log1p keeps full relative precision).
// Stage 3 (finalize): average the 3 pair losses into d_out[0].
// ---------------------------------------------------------------------------

#define BROWS 16               // batch rows per tensor
#define ZROWS 32               // teacher rows 0..15, rec rows 16..31
#define TK    128              // k-chunk per block iteration
#define SHP   129              // smem pitch (129 % 32 == 1 -> conflict-free)
#define NWARPS 21              // 20 gram warps + 1 sum warp
#define NTHREADS (NWARPS * 32) // 672
#define NLD 7                  // ceil(32*128 / 672)

__device__ double g_gram[3][32][32];
__device__ double g_sums[3][32];
__device__ double g_partial[3];

// 4x8 tiles covering the upper triangle of the 32x32 Gram (20 tiles).
__constant__ unsigned char c_tra[20] = {0,0,0,0, 1,1,1,1, 2,2,2, 3,3,3, 4,4, 5,5, 6, 7};
__constant__ unsigned char c_tcb[20] = {0,1,2,3, 0,1,2,3, 1,2,3, 1,2,3, 2,3, 2,3, 3, 3};

__global__ void zero_kernel() {
    int tid = threadIdx.x;
    double* g = &g_gram[0][0][0];
    for (int i = tid; i < 3 * 32 * 32; i += blockDim.x) g[i] = 0.0;
    if (tid < 96) g_sums[tid >> 5][tid & 31] = 0.0;
    if (tid < 3)  g_partial[tid] = 0.0;
}

__global__ void __launch_bounds__(NTHREADS, 1)
gram_kernel(const float* __restrict__ T0, const float* __restrict__ R0, int M0, int nb0,
            const float* __restrict__ T1, const float* __restrict__ R1, int M1, int nb1,
            const float* __restrict__ T2, const float* __restrict__ R2, int M2, int nb2)
{
    __shared__ float sh[ZROWS * SHP];

    const int tid  = threadIdx.x;
    const int wid  = tid >> 5;
    const int lane = tid & 31;

    // --- pick pair for this block ---
    const float *T, *R; int M, lb, nb, pair;
    int b = blockIdx.x;
    if (b < nb0)            { T = T0; R = R0; M = M0; lb = b;             nb = nb0; pair = 0; }
    else if (b < nb0 + nb1) { T = T1; R = R1; M = M1; lb = b - nb0;       nb = nb1; pair = 1; }
    else                    { T = T2; R = R2; M = M2; lb = b - nb0 - nb1; nb = nb2; pair = 2; }

    // --- per-slot load constants (coalesced: consecutive tid -> consecutive col) ---
    const float* bp[NLD];
    int  shidx[NLD];
    bool vld[NLD];
#pragma unroll
    for (int t = 0; t < NLD; t++) {
        int idx = tid + t * NTHREADS;          // 0 .. 4703, valid < 4096
        vld[t] = (idx < ZROWS * TK);
        int row = vld[t] ? (idx >> 7) : 0;
        int col = vld[t] ? (idx & 127) : 0;
        const float* base = (row < BROWS) ? (T + (size_t)row * (size_t)M)
                                          : (R + (size_t)(row - BROWS) * (size_t)M);
        bp[t]    = base + col;
        shidx[t] = row * SHP + col;
    }

    // --- tile assignment (gram warps) ---
    int rbase = 0, cbase = 0;
    if (wid < 20) { rbase = (int)c_tra[wid] * 4; cbase = (int)c_tcb[wid] * 8; }

    float acc[4][8];
#pragma unroll
    for (int r = 0; r < 4; r++)
#pragma unroll
        for (int c = 0; c < 8; c++) acc[r][c] = 0.f;
    float s0 = 0.f, s1 = 0.f, s2 = 0.f, s3 = 0.f;   // sum warp partials

    const int nchunks = M >> 7;

    // --- prefetch first chunk into registers ---
    float v[NLD];
    {
        int k0 = lb << 7;
#pragma unroll
        for (int t = 0; t < NLD; t++) v[t] = vld[t] ? __ldg(bp[t] + k0) : 0.f;
    }

    for (int ci = lb; ci < nchunks; ci += nb) {
        // stage exp(values) into smem (conflict-free: bank = (row+col)%32)
#pragma unroll
        for (int t = 0; t < NLD; t++)
            if (vld[t]) sh[shidx[t]] = __expf(v[t]);
        __syncthreads();

        // prefetch next chunk's raw values (overlaps with FMA phase below)
        int cn = ci + nb;
        if (cn < nchunks) {
            int kn = cn << 7;
#pragma unroll
            for (int t = 0; t < NLD; t++)
                if (vld[t]) v[t] = __ldg(bp[t] + kn);
        }

        if (wid < 20) {
            // gram warp: 4x8 output tile, lanes are k-slices (conflict-free LDS)
#pragma unroll
            for (int it = 0; it < 4; it++) {
                int k = (it << 5) + lane;
                float za[4], zb[8];
#pragma unroll
                for (int r = 0; r < 4; r++) za[r] = sh[(rbase + r) * SHP + k];
#pragma unroll
                for (int c = 0; c < 8; c++) zb[c] = sh[(cbase + c) * SHP + k];
#pragma unroll
                for (int r = 0; r < 4; r++)
#pragma unroll
                    for (int c = 0; c < 8; c++)
                        acc[r][c] = fmaf(za[r], zb[c], acc[r][c]);
            }
        } else {
            // sum warp: lane = row, sum 128 k values (all lanes same k -> no conflicts)
            const float* rp = &sh[lane * SHP];
#pragma unroll 8
            for (int k = 0; k < TK; k += 4) {
                s0 += rp[k]; s1 += rp[k + 1]; s2 += rp[k + 2]; s3 += rp[k + 3];
            }
        }
        __syncthreads();
    }

    // --- fold partials into fp64 global accumulators ---
    if (wid < 20) {
#pragma unroll
        for (int r = 0; r < 4; r++)
#pragma unroll
            for (int c = 0; c < 8; c++) {
                float x = acc[r][c];
                x += __shfl_xor_sync(0xffffffffu, x, 16);
                x += __shfl_xor_sync(0xffffffffu, x, 8);
                x += __shfl_xor_sync(0xffffffffu, x, 4);
                x += __shfl_xor_sync(0xffffffffu, x, 2);
                x += __shfl_xor_sync(0xffffffffu, x, 1);
                if (lane == (r * 8 + c))
                    atomicAdd(&g_gram[pair][rbase + r][cbase + c], (double)x);
            }
    } else {
        float s = (s0 + s1) + (s2 + s3);
        atomicAdd(&g_sums[pair][lane], (double)s);
    }
}

// ---------------------------------------------------------------------------
// Sinkhorn solver: 3 blocks (one per pair), 1024 threads = 4 softmins x 16 x 16
// ---------------------------------------------------------------------------
__global__ void __launch_bounds__(1024, 1)
solver_kernel()
{
    const int p = blockIdx.x;
    __shared__ float Cxy[16][16], Cxx[16][16], Cyy[16][16];
    __shared__ float pot[2][4][16];
    __shared__ float fin[4][16];
    __shared__ float epss[60];
    __shared__ double Ssh[32];

    const int tid = threadIdx.x;
    const int q = tid >> 8;
    const int i = (tid >> 4) & 15;
    const int j = tid & 15;

    if (tid < 32) Ssh[tid] = g_sums[p][tid];
    if (tid < 60) {
        double e = pow(0.9025, (double)tid);         // (scaling^p)^k
        epss[tid] = (float)fmax(e, 0.0025);          // clamped at blur^p
    }
    if (tid < 64) pot[0][tid >> 4][tid & 15] = 0.f;  // zero-init potentials
    __syncthreads();

    if (tid < 256) {
        int ii = tid >> 4, jj = tid & 15;
        double Si  = Ssh[ii],        Sj  = Ssh[jj];
        double Syi = Ssh[16 + ii],   Syj = Ssh[16 + jj];
        double a2i = g_gram[p][ii][ii] / (Si * Si);
        double a2j = g_gram[p][jj][jj] / (Sj * Sj);
        double b2i = g_gram[p][16 + ii][16 + ii] / (Syi * Syi);
        double b2j = g_gram[p][16 + jj][16 + jj] / (Syj * Syj);
        double dxy = g_gram[p][ii][16 + jj] / (Si * Syj);
        int lo = min(ii, jj), hi = max(ii, jj);
        double dxx = g_gram[p][lo][hi]           / (Si * Sj);
        double dyy = g_gram[p][16 + lo][16 + hi] / (Syi * Syj);
        Cxy[ii][jj] = (float)(0.5 * (a2i + b2j) - dxy);
        Cxx[ii][jj] = (float)(0.5 * (a2i + a2j) - dxx);
        Cyy[ii][jj] = (float)(0.5 * (b2i + b2j) - dyy);
    }
    __syncthreads();

    int cur = 0;
    for (int s = 0; s < 60; s++) {
        float eps = epss[s];
        float inv_eps = 1.0f / eps;
        float h, Cv, old;
        if (q == 0)      { h = pot[cur][1][j]; Cv = Cxy[i][j]; old = pot[cur][0][i]; }
        else if (q == 1) { h = pot[cur][0][j]; Cv = Cxy[j][i]; old = pot[cur][1][i]; }
        else if (q == 2) { h = pot[cur][2][j]; Cv = Cxx[i][j]; old = pot[cur][2][i]; }
        else             { h = pot[cur][3][j]; Cv = Cyy[i][j]; old = pot[cur][3][i]; }
        float t = expm1f((h - Cv) * inv_eps);
        t += __shfl_xor_sync(0xffffffffu, t, 1);
        t += __shfl_xor_sync(0xffffffffu, t, 2);
        t += __shfl_xor_sync(0xffffffffu, t, 4);
        t += __shfl_xor_sync(0xffffffffu, t, 8);
        if (j == 0)
            pot[cur ^ 1][q][i] = 0.5f * (old - eps * log1pf(t * 0.0625f));
        __syncthreads();
        cur ^= 1;
    }

    // final extrapolation at eps = blur^p = 0.0025 (no averaging)
    {
        const float eps = 0.0025f;
        const float inv_eps = 1.0f / eps;
        float h, Cv;
        if (q == 0)      { h = pot[cur][1][j]; Cv = Cxy[i][j]; }
        else if (q == 1) { h = pot[cur][0][j]; Cv = Cxy[j][i]; }
        else if (q == 2) { h = pot[cur][2][j]; Cv = Cxx[i][j]; }
        else             { h = pot[cur][3][j]; Cv = Cyy[i][j]; }
        float t = expm1f((h - Cv) * inv_eps);
        t += __shfl_xor_sync(0xffffffffu, t, 1);
        t += __shfl_xor_sync(0xffffffffu, t, 2);
        t += __shfl_xor_sync(0xffffffffu, t, 4);
        t += __shfl_xor_sync(0xffffffffu, t, 8);
        if (j == 0) fin[q][i] = -eps * log1pf(t * 0.0625f);
        __syncthreads();
    }

    if (tid == 0) {
        double acc = 0.0;
        for (int ii = 0; ii < 16; ii++)
            acc += ((double)fin[0][ii] - (double)fin[2][ii])
                 + ((double)fin[1][ii] - (double)fin[3][ii]);
        g_partial[p] = acc / 16.0;
    }
}

__global__ void finalize_kernel(float* out) {
    out[0] = (float)((g_partial[0] + g_partial[1] + g_partial[2]) / 3.0);
}

// ---------------------------------------------------------------------------
extern "C" void kernel_launch(void* const* d_in, const int* in_sizes, int n_in,
                              void* d_out, int out_size)
{
    (void)out_size;
    // Group the 6 inputs into 3 pairs by element count (sinkhorn divergence is
    // symmetric in (x, y), so teacher/rec order within a pair is irrelevant).
    int idx[6] = {0, 1, 2, 3, 4, 5};
    int n = (n_in < 6) ? n_in : 6;
    for (int a = 0; a < n; a++)
        for (int b = a + 1; b < n; b++)
            if (in_sizes[idx[b]] > in_sizes[idx[a]]) {
                int tmp = idx[a]; idx[a] = idx[b]; idx[b] = tmp;
            }

    const float* T[3]; const float* R[3]; int M[3]; int nb[3];
    for (int p = 0; p < 3; p++) {
        T[p] = (const float*)d_in[idx[2 * p]];
        R[p] = (const float*)d_in[idx[2 * p + 1]];
        M[p] = in_sizes[idx[2 * p]] / BROWS;   // per-row length
        int chunks = M[p] >> 7;                // TK = 128
        nb[p] = chunks / 97;                   // ~1 wave over 148 SMs total
        if (nb[p] < 1) nb[p] = 1;
        if (nb[p] > chunks) nb[p] = chunks;
    }

    zero_kernel<<<1, 256>>>();
    gram_kernel<<<nb[0] + nb[1] + nb[2], NTHREADS>>>(
        T[0], R[0], M[0], nb[0],
        T[1], R[1], M[1], nb[1],
        T[2], R[2], M[2], nb[2]);
    solver_kernel<<<3, 1024>>>();
    finalize_kernel<<<1, 1>>>((float*)d_out);
}

// round 5
// speedup vs baseline: 1.6586x; 1.6586x over previous
#include <cuda_runtime.h>
#include <math.h>

// ---------------------------------------------------------------------------
// Revisit_RDLoss: debiased Sinkhorn divergence over softmax rows, 3 pairs.
//
// Stage 1 (gram_kernel): Z = [exp(teacher); exp(rec)] (32 rows x M).
//   G = Z Z^T (upper triangle) + row sums S. Staging: exp values packed to
//   bf16x2 in smem (halves crossbar bytes); compute: packed fma.rn.f32x2
//   (FFMA2) on 8x8 tiles, exact 528-entry upper-triangle coverage with
//   8 warps (6 off-diag 8x8 + 2 double-diagonal-triangle), SMSP-balanced.
//   fp32 partials -> fp64 atomics. Softmax normalization factors out.
// Stage 2 (solver_kernel): build C (fp64->fp32), 60-step eps-scaled Sinkhorn
//   with softmin_i = -eps*log1p(mean_j expm1((h_j-C_ij)/eps)); since
//   |u|<~1e-2, expm1/log1p are replaced by cubic Taylor (rel err <1e-8).
//   Each pair block atomicAdds its loss/3 into d_out (zeroed by zero_kernel).
// ---------------------------------------------------------------------------

#define BROWS 16
#define NTHR  256               // 8 warps

__device__ double g_gram[3][32][32];
__device__ double g_sums[3][32];

// warp -> tile: warps 3 and 6 are "diag" warps (two 8x8 diagonal triangles),
// others are off-diagonal 8x8 tiles (rb < cb).
// SMSP load (entries): S0: w0,w4 = 64+64; S1: w1,w5 = 64+64;
//                      S2: w2,w6 = 64+72; S3: w3,w7 = 72+64.  (balanced)
__constant__ unsigned char c_rb[8] = {0, 0, 0, 0, 1, 1, 2, 2};
__constant__ unsigned char c_cb[8] = {1, 2, 3, 0, 2, 3, 0, 3};

// ---- f32x2 / bf16x2 helpers -------------------------------------------------
__device__ __forceinline__ unsigned long long ffma2(unsigned long long a,
                                                    unsigned long long b,
                                                    unsigned long long c) {
    unsigned long long d;
    asm("fma.rn.f32x2 %0, %1, %2, %3;" : "=l"(d) : "l"(a), "l"(b), "l"(c));
    return d;
}

// bf16x2 (lo = even k, hi = odd k) -> f32x2 packed pair
__device__ __forceinline__ unsigned long long bf2_to_f32x2(unsigned int v) {
    unsigned long long z;
    asm("{\n\t"
        ".reg .b32 lo, hi;\n\t"
        "shl.b32 lo, %1, 16;\n\t"
        "and.b32 hi, %1, 0xffff0000;\n\t"
        "mov.b64 %0, {lo, hi};\n\t"
        "}" : "=l"(z) : "r"(v));
    return z;
}

__device__ __forceinline__ unsigned int pack_bf16x2(float hi, float lo) {
    unsigned int r;
    asm("cvt.rn.bf16x2.f32 %0, %1, %2;" : "=r"(r) : "f"(hi), "f"(lo));
    return r;
}

__device__ __forceinline__ float f32x2_sum(unsigned long long v) {
    unsigned int lo, hi;
    asm("mov.b64 {%0, %1}, %2;" : "=r"(lo), "=r"(hi) : "l"(v));
    return __uint_as_float(lo) + __uint_as_float(hi);
}

__device__ __forceinline__ float warp_sum(float x) {
    x += __shfl_xor_sync(0xffffffffu, x, 16);
    x += __shfl_xor_sync(0xffffffffu, x, 8);
    x += __shfl_xor_sync(0xffffffffu, x, 4);
    x += __shfl_xor_sync(0xffffffffu, x, 2);
    x += __shfl_xor_sync(0xffffffffu, x, 1);
    return x;
}

__global__ void zero_kernel(float* out) {
    int tid = threadIdx.x;
    double* g = &g_gram[0][0][0];
    for (int i = tid; i < 3 * 32 * 32; i += blockDim.x) g[i] = 0.0;
    if (tid < 96) g_sums[tid >> 5][tid & 31] = 0.0;
    if (tid == 0) out[0] = 0.0f;
}

__global__ void __launch_bounds__(NTHR, 1)
gram_kernel(const float* __restrict__ T0, const float* __restrict__ R0, int M0, int nb0,
            const float* __restrict__ T1, const float* __restrict__ R1, int M1, int nb1,
            const float* __restrict__ T2, const float* __restrict__ R2, int M2, int nb2)
{
    // 32 rows x 128 bf16 (= 32 x 32 ull). Row pitch 64 u32; all accesses are
    // row-contiguous -> bank-conflict-free.
    __shared__ unsigned long long shll[32 * 32];
    unsigned int* shu = (unsigned int*)shll;

    const int tid  = threadIdx.x;
    const int wid  = tid >> 5;
    const int lane = tid & 31;

    // --- pick pair ---
    const float *T, *R; int M, lb, nb, pair;
    int b = blockIdx.x;
    if (b < nb0)            { T = T0; R = R0; M = M0; lb = b;             nb = nb0; pair = 0; }
    else if (b < nb0 + nb1) { T = T1; R = R1; M = M1; lb = b - nb0;       nb = nb1; pair = 1; }
    else                    { T = T2; R = R2; M = M2; lb = b - nb0 - nb1; nb = nb2; pair = 2; }

    // --- loader: 4 float4 slots per thread (1024 slots = 32 rows x 32 f4) ---
    // slot s = tid + 256*t: row = s>>5 = wid + 8t (all lanes of a warp share rows)
    const float4* gp[4];
    int shq[4];
    float rsum[4] = {0.f, 0.f, 0.f, 0.f};
#pragma unroll
    for (int t = 0; t < 4; t++) {
        int s = tid + t * NTHR;
        int row = s >> 5, c4 = s & 31;
        const float* base = (row < BROWS) ? (T + (size_t)row * (size_t)M)
                                          : (R + (size_t)(row - BROWS) * (size_t)M);
        gp[t]  = (const float4*)base + c4;
        shq[t] = row * 32 + c4;            // ull index
    }

    const int rb = (int)c_rb[wid];
    const int cb = (int)c_cb[wid];
    const bool isdiag = (wid == 3) || (wid == 6);

    unsigned long long acc[72];
#pragma unroll
    for (int e = 0; e < 72; e++) acc[e] = 0ull;

    const int nchunks = M >> 7;

    // prefetch first chunk
    float4 v[4];
    {
        int q0 = lb * 32;
#pragma unroll
        for (int t = 0; t < 4; t++) v[t] = __ldg(gp[t] + q0);
    }

    for (int ci = lb; ci < nchunks; ci += nb) {
        // ---- stage exp(values) as bf16x2 into smem, accumulate row sums ----
#pragma unroll
        for (int t = 0; t < 4; t++) {
            float e0 = __expf(v[t].x), e1 = __expf(v[t].y);
            float e2 = __expf(v[t].z), e3 = __expf(v[t].w);
            rsum[t] += (e0 + e1) + (e2 + e3);
            unsigned int p0 = pack_bf16x2(e1, e0);
            unsigned int p1 = pack_bf16x2(e3, e2);
            unsigned long long pk;
            asm("mov.b64 %0, {%1, %2};" : "=l"(pk) : "r"(p0), "r"(p1));
            shll[shq[t]] = pk;
        }
        __syncthreads();

        // prefetch next chunk (overlaps the FMA phase)
        int cn = ci + nb;
        if (cn < nchunks) {
            int q = cn * 32;
#pragma unroll
            for (int t = 0; t < 4; t++) v[t] = __ldg(gp[t] + q);
        }

        // ---- FFMA2 phase: lane owns k-pair (2*kw, 2*kw+1) ----
        if (!isdiag) {
#pragma unroll
            for (int h = 0; h < 2; h++) {
                int kw = (h << 5) + lane;
                unsigned long long za[8];
#pragma unroll
                for (int r = 0; r < 8; r++)
                    za[r] = bf2_to_f32x2(shu[(rb * 8 + r) * 64 + kw]);
#pragma unroll
                for (int c = 0; c < 8; c++) {
                    unsigned long long zb = bf2_to_f32x2(shu[(cb * 8 + c) * 64 + kw]);
#pragma unroll
                    for (int r = 0; r < 8; r++)
                        acc[(r << 3) + c] = ffma2(za[r], zb, acc[(r << 3) + c]);
                }
            }
        } else {
#pragma unroll
            for (int h = 0; h < 2; h++) {
                int kw = (h << 5) + lane;
#pragma unroll
                for (int blk = 0; blk < 2; blk++) {
                    int rbase = (rb + blk) * 8;
                    unsigned long long z[8];
#pragma unroll
                    for (int r = 0; r < 8; r++)
                        z[r] = bf2_to_f32x2(shu[(rbase + r) * 64 + kw]);
                    int e = blk * 36;
#pragma unroll
                    for (int r = 0; r < 8; r++)
#pragma unroll
                        for (int c = r; c < 8; c++) {
                            acc[e] = ffma2(z[r], z[c], acc[e]);
                            e++;
                        }
                }
            }
        }
        __syncthreads();
    }

    // ---- fold Gram partials into fp64 globals ----
    if (!isdiag) {
#pragma unroll
        for (int rc = 0; rc < 64; rc++) {
            float x = warp_sum(f32x2_sum(acc[rc]));
            if (lane == (rc & 31))
                atomicAdd(&g_gram[pair][rb * 8 + (rc >> 3)][cb * 8 + (rc & 7)], (double)x);
        }
    } else {
        int e = 0;
#pragma unroll
        for (int blk = 0; blk < 2; blk++) {
            int rbase = (rb + blk) * 8;
#pragma unroll
            for (int r = 0; r < 8; r++)
#pragma unroll
                for (int c = r; c < 8; c++) {
                    float x = warp_sum(f32x2_sum(acc[e]));
                    if (lane == (e & 31))
                        atomicAdd(&g_gram[pair][rbase + r][rbase + c], (double)x);
                    e++;
                }
        }
    }

    // ---- row sums: warp w's slot t is row (w + 8t) ----
#pragma unroll
    for (int t = 0; t < 4; t++) {
        float s = warp_sum(rsum[t]);
        if (lane == 0)
            atomicAdd(&g_sums[pair][wid + (t << 3)], (double)s);
    }
}

// ---------------------------------------------------------------------------
// Sinkhorn solver: 3 blocks (one per pair), 1024 threads = 4 softmins x 16x16.
// expm1/log1p via cubic Taylor (|u| <= ~1e-2 for this problem).
// ---------------------------------------------------------------------------
__global__ void __launch_bounds__(1024, 1)
solver_kernel(float* out)
{
    const int p = blockIdx.x;
    __shared__ float Cxy[16][16], Cxx[16][16], Cyy[16][16];
    __shared__ float pot[2][4][16];
    __shared__ float fin[4][16];
    __shared__ float epss[60];
    __shared__ double Ssh[32];

    const int tid = threadIdx.x;
    const int q = tid >> 8;
    const int i = (tid >> 4) & 15;
    const int j = tid & 15;

    if (tid < 32) Ssh[tid] = g_sums[p][tid];
    if (tid < 60) {
        double e = pow(0.9025, (double)tid);
        epss[tid] = (float)fmax(e, 0.0025);
    }
    if (tid < 64) pot[0][tid >> 4][tid & 15] = 0.f;
    __syncthreads();

    if (tid < 256) {
        int ii = tid >> 4, jj = tid & 15;
        double Si  = Ssh[ii],      Sj  = Ssh[jj];
        double Syi = Ssh[16 + ii], Syj = Ssh[16 + jj];
        double a2i = g_gram[p][ii][ii] / (Si * Si);
        double a2j = g_gram[p][jj][jj] / (Sj * Sj);
        double b2i = g_gram[p][16 + ii][16 + ii] / (Syi * Syi);
        double b2j = g_gram[p][16 + jj][16 + jj] / (Syj * Syj);
        double dxy = g_gram[p][ii][16 + jj] / (Si * Syj);
        int lo = min(ii, jj), hi = max(ii, jj);
        double dxx = g_gram[p][lo][hi]           / (Si * Sj);
        double dyy = g_gram[p][16 + lo][16 + hi] / (Syi * Syj);
        Cxy[ii][jj] = (float)(0.5 * (a2i + b2j) - dxy);
        Cxx[ii][jj] = (float)(0.5 * (a2i + a2j) - dxx);
        Cyy[ii][jj] = (float)(0.5 * (b2i + b2j) - dyy);
    }
    __syncthreads();

    int cur = 0;
    for (int s = 0; s < 60; s++) {
        float eps = epss[s];
        float inv_eps = 1.0f / eps;
        float h, Cv, old;
        if (q == 0)      { h = pot[cur][1][j]; Cv = Cxy[i][j]; old = pot[cur][0][i]; }
        else if (q == 1) { h = pot[cur][0][j]; Cv = Cxy[j][i]; old = pot[cur][1][i]; }
        else if (q == 2) { h = pot[cur][2][j]; Cv = Cxx[i][j]; old = pot[cur][2][i]; }
        else             { h = pot[cur][3][j]; Cv = Cyy[i][j]; old = pot[cur][3][i]; }
        float u = (h - Cv) * inv_eps;
        // expm1(u) ~= u + u^2/2 + u^3/6
        float t = u * fmaf(u, fmaf(u, 0.16666667f, 0.5f), 1.0f);
        t += __shfl_xor_sync(0xffffffffu, t, 1);
        t += __shfl_xor_sync(0xffffffffu, t, 2);
        t += __shfl_xor_sync(0xffffffffu, t, 4);
        t += __shfl_xor_sync(0xffffffffu, t, 8);
        if (j == 0) {
            float m = t * 0.0625f;
            // log1p(m) ~= m - m^2/2 + m^3/3
            float l = m * fmaf(m, fmaf(m, 0.33333333f, -0.5f), 1.0f);
            pot[cur ^ 1][q][i] = 0.5f * (old - eps * l);
        }
        __syncthreads();
        cur ^= 1;
    }

    // final extrapolation at eps = 0.0025
    {
        const float eps = 0.0025f;
        const float inv_eps = 1.0f / eps;
        float h, Cv;
        if (q == 0)      { h = pot[cur][1][j]; Cv = Cxy[i][j]; }
        else if (q == 1) { h = pot[cur][0][j]; Cv = Cxy[j][i]; }
        else if (q == 2) { h = pot[cur][2][j]; Cv = Cxx[i][j]; }
        else             { h = pot[cur][3][j]; Cv = Cyy[i][j]; }
        float u = (h - Cv) * inv_eps;
        float t = u * fmaf(u, fmaf(u, 0.16666667f, 0.5f), 1.0f);
        t += __shfl_xor_sync(0xffffffffu, t, 1);
        t += __shfl_xor_sync(0xffffffffu, t, 2);
        t += __shfl_xor_sync(0xffffffffu, t, 4);
        t += __shfl_xor_sync(0xffffffffu, t, 8);
        if (j == 0) {
            float m = t * 0.0625f;
            float l = m * fmaf(m, fmaf(m, 0.33333333f, -0.5f), 1.0f);
            fin[q][i] = -eps * l;
        }
        __syncthreads();
    }

    if (tid == 0) {
        double acc = 0.0;
        for (int ii = 0; ii < 16; ii++)
            acc += ((double)fin[0][ii] - (double)fin[2][ii])
                 + ((double)fin[1][ii] - (double)fin[3][ii]);
        atomicAdd(out, (float)(acc / 48.0));   // mean over 16, averaged over 3 pairs
    }
}

// ---------------------------------------------------------------------------
extern "C" void kernel_launch(void* const* d_in, const int* in_sizes, int n_in,
                              void* d_out, int out_size)
{
    (void)out_size;
    // Pair the 6 inputs by element count (divergence is symmetric in (x, y)).
    int idx[6] = {0, 1, 2, 3, 4, 5};
    int n = (n_in < 6) ? n_in : 6;
    for (int a = 0; a < n; a++)
        for (int b = a + 1; b < n; b++)
            if (in_sizes[idx[b]] > in_sizes[idx[a]]) {
                int tmp = idx[a]; idx[a] = idx[b]; idx[b] = tmp;
            }

    const float* T[3]; const float* R[3]; int M[3]; int nb[3];
    for (int p = 0; p < 3; p++) {
        T[p] = (const float*)d_in[idx[2 * p]];
        R[p] = (const float*)d_in[idx[2 * p + 1]];
        M[p] = in_sizes[idx[2 * p]] / BROWS;
        int chunks = M[p] >> 7;
        nb[p] = chunks / 97;
        if (nb[p] < 1) nb[p] = 1;
        if (nb[p] > chunks) nb[p] = chunks;
    }

    zero_kernel<<<1, 256>>>((float*)d_out);
    gram_kernel<<<nb[0] + nb[1] + nb[2], NTHR>>>(
        T[0], R[0], M[0], nb[0],
        T[1], R[1], M[1], nb[1],
        T[2], R[2], M[2], nb[2]);
    solver_kernel<<<3, 1024>>>((float*)d_out);
}

// round 6
// speedup vs baseline: 2.5712x; 1.5502x over previous
#include <cuda_runtime.h>
#include <math.h>
#include <stdint.h>

// ---------------------------------------------------------------------------
// Revisit_RDLoss: debiased Sinkhorn divergence over softmax rows, 3 pairs.
//
// Stage 1 (gram_kernel, tensor-core version):
//   Z = [exp(teacher); exp(rec)] (32 rows x M). G = Z Z^T + row sums S.
//   Per 256-K iteration: 512 threads load 32 KB fp32, exp+pack to bf16 into a
//   SW128-swizzled smem tile (4 sub-tiles of 32 rows x 128B), double-buffered,
//   one __syncthreads per iteration. 16 warps each own one k16-step and
//   compute the full 32x32 output via mma.sync.m16n8k16 (bf16->f32):
//   2 ldmatrix.x4 per warp (rows 0-15, 16-31) serve as BOTH the A-fragments
//   and the B-fragments (Gram symmetry), 8 HMMA per warp per iteration.
//   fp32 c-frag accumulators across all iterations; block combine in smem
//   (fp32) then one fp64 atomicAdd per Gram entry per block.
// Stage 2 (solver_kernel): build C from G,S (fp64->fp32); 60-step eps-scaled
//   Sinkhorn, softmin via -eps*log1p(mean_j expm1(u)) with cubic Taylor
//   (|u| <= ~1e-2 here); each pair block atomicAdds loss/3 into d_out.
// ---------------------------------------------------------------------------

#define BROWS 16
#define NTHR  512            // 16 warps
#define TKI   256            // K elements per iteration
#define BUFB  16384          // bytes per smem buffer (4 tiles x 4096)

__device__ double g_gram[3][32][32];
__device__ double g_sums[3][32];

// ---- PTX helpers ------------------------------------------------------------
#define LDSM_X4(r0, r1, r2, r3, a)                                          \
    asm volatile("ldmatrix.sync.aligned.x4.m8n8.shared.b16 {%0,%1,%2,%3}, [%4];" \
                 : "=r"(r0), "=r"(r1), "=r"(r2), "=r"(r3) : "r"(a))

#define MMA16816(c, a0, a1, a2, a3, b0, b1)                                 \
    asm volatile("mma.sync.aligned.m16n8k16.row.col.f32.bf16.bf16.f32 "     \
                 "{%0,%1,%2,%3}, {%4,%5,%6,%7}, {%8,%9}, {%0,%1,%2,%3};"    \
                 : "+f"((c)[0]), "+f"((c)[1]), "+f"((c)[2]), "+f"((c)[3])   \
                 : "r"(a0), "r"(a1), "r"(a2), "r"(a3), "r"(b0), "r"(b1))

__device__ __forceinline__ unsigned int pack_bf16x2(float hi, float lo) {
    unsigned int r;
    asm("cvt.rn.bf16x2.f32 %0, %1, %2;" : "=r"(r) : "f"(hi), "f"(lo));
    return r;
}

__device__ __forceinline__ void sts64(unsigned int addr, unsigned int p0, unsigned int p1) {
    asm volatile("st.shared.v2.b32 [%0], {%1, %2};" :: "r"(addr), "r"(p0), "r"(p1));
}

__global__ void zero_kernel(float* out) {
    int tid = threadIdx.x;
    double* g = &g_gram[0][0][0];
    for (int i = tid; i < 3 * 32 * 32; i += blockDim.x) g[i] = 0.0;
    if (tid < 96) g_sums[tid >> 5][tid & 31] = 0.0;
    if (tid == 0) out[0] = 0.0f;
}

__global__ void __launch_bounds__(NTHR, 1)
gram_kernel(const float* __restrict__ T0, const float* __restrict__ R0, int M0, int nb0,
            const float* __restrict__ T1, const float* __restrict__ R1, int M1, int nb1,
            const float* __restrict__ T2, const float* __restrict__ R2, int M2, int nb2)
{
    __shared__ __align__(16) char smem_raw[2 * BUFB];
    const uint32_t sbase = (uint32_t)__cvta_generic_to_shared(smem_raw);

    const int tid  = threadIdx.x;
    const int wid  = tid >> 5;
    const int lane = tid & 31;

    // --- pick pair ---
    const float *T, *R; int M, lb, nb, pair;
    int b = blockIdx.x;
    if (b < nb0)            { T = T0; R = R0; M = M0; lb = b;             nb = nb0; pair = 0; }
    else if (b < nb0 + nb1) { T = T1; R = R1; M = M1; lb = b - nb0;       nb = nb1; pair = 1; }
    else                    { T = T2; R = R2; M = M2; lb = b - nb0 - nb1; nb = nb2; pair = 2; }

    // --- loader mapping: row = tid>>4 (constant per thread), c4 = tid&15,
    //     k-quarter = slot t. Row r of sub-tile q = 128B, SW128 swizzle. ---
    const int row = tid >> 4;
    const int c4  = tid & 15;
    const float* rbase = (row < BROWS) ? (T + (size_t)row * (size_t)M)
                                       : (R + (size_t)(row - BROWS) * (size_t)M);
    const float4* g4 = (const float4*)rbase + c4;

    const int sts_off = (row * 128 + c4 * 8) ^ ((row & 7) << 4);
    const uint32_t sts0 = sbase + sts_off;
    const uint32_t sts1 = sts0 + BUFB;

    // --- ldmatrix addresses: warp wid owns k16-step wid ---
    const int q  = wid >> 2;            // sub-tile (k quarter)
    const int ko = (wid & 3) * 32;      // byte offset of k16 within 128B row
    const int kb = (lane & 16);         // 0 / 16 bytes (klo / khi matrices)
    const int rw = lane & 15;
    int oA = rw * 128 + ko + kb;        oA = q * 4096 + (oA ^ ((rw & 7) << 4));
    int rB = rw + 16;
    int oB = rB * 128 + ko + kb;        oB = q * 4096 + (oB ^ ((rB & 7) << 4));
    const uint32_t lds00 = sbase + oA, lds01 = sbase + oB;        // buf0
    const uint32_t lds10 = lds00 + BUFB, lds11 = lds01 + BUFB;    // buf1

    float acc[8][4];
#pragma unroll
    for (int i = 0; i < 8; i++)
#pragma unroll
        for (int jj = 0; jj < 4; jj++) acc[i][jj] = 0.f;
    float rsum = 0.f;

    const int niter = M >> 8;                       // TKI = 256
    const int cnt = (niter - lb + nb - 1) / nb;

    float4 vA[4], vB[4];
#pragma unroll
    for (int t = 0; t < 4; t++)
        vA[t] = __ldg(g4 + (size_t)lb * 64 + t * 16);
    if (cnt > 1) {
#pragma unroll
        for (int t = 0; t < 4; t++)
            vB[t] = __ldg(g4 + (size_t)(lb + nb) * 64 + t * 16);
    }

    // stage: exp+pack bank -> smem buffer
    auto stage = [&](float4* v, uint32_t sts) {
#pragma unroll
        for (int t = 0; t < 4; t++) {
            float e0 = __expf(v[t].x), e1 = __expf(v[t].y);
            float e2 = __expf(v[t].z), e3 = __expf(v[t].w);
            rsum += (e0 + e1) + (e2 + e3);
            sts64(sts + t * 4096, pack_bf16x2(e1, e0), pack_bf16x2(e3, e2));
        }
    };
    auto mma_phase = [&](uint32_t a0addr, uint32_t a1addr) {
        uint32_t L0[4], L1[4];
        LDSM_X4(L0[0], L0[1], L0[2], L0[3], a0addr);   // rows 0-15
        LDSM_X4(L1[0], L1[1], L1[2], L1[3], a1addr);   // rows 16-31
        // m rows 0-15
        MMA16816(acc[0], L0[0], L0[1], L0[2], L0[3], L0[0], L0[2]);  // n 0-7
        MMA16816(acc[1], L0[0], L0[1], L0[2], L0[3], L0[1], L0[3]);  // n 8-15
        MMA16816(acc[2], L0[0], L0[1], L0[2], L0[3], L1[0], L1[2]);  // n 16-23
        MMA16816(acc[3], L0[0], L0[1], L0[2], L0[3], L1[1], L1[3]);  // n 24-31
        // m rows 16-31
        MMA16816(acc[4], L1[0], L1[1], L1[2], L1[3], L0[0], L0[2]);
        MMA16816(acc[5], L1[0], L1[1], L1[2], L1[3], L0[1], L0[3]);
        MMA16816(acc[6], L1[0], L1[1], L1[2], L1[3], L1[0], L1[2]);
        MMA16816(acc[7], L1[0], L1[1], L1[2], L1[3], L1[1], L1[3]);
    };

    int j = 0;
    while (true) {
        // even iteration: bank A, buffer 0
        stage(vA, sts0);
        {
            int pf = lb + (j + 2) * nb;
            if (pf < niter) {
#pragma unroll
                for (int t = 0; t < 4; t++)
                    vA[t] = __ldg(g4 + (size_t)pf * 64 + t * 16);
            }
        }
        __syncthreads();
        mma_phase(lds00, lds01);
        j++; if (j >= cnt) break;

        // odd iteration: bank B, buffer 1
        stage(vB, sts1);
        {
            int pf = lb + (j + 2) * nb;
            if (pf < niter) {
#pragma unroll
                for (int t = 0; t < 4; t++)
                    vB[t] = __ldg(g4 + (size_t)pf * 64 + t * 16);
            }
        }
        __syncthreads();
        mma_phase(lds10, lds11);
        j++; if (j >= cnt) break;
    }

    // --- block-level combine (reuse staging smem) ---
    __syncthreads();                    // all mma reads done
    float* gc = (float*)smem_raw;       // [32][33]
    float* rs = gc + 32 * 33;           // [32]
    for (int i = tid; i < 32 * 33 + 32; i += NTHR) gc[i] = 0.f;
    __syncthreads();

    {
        const int fr = lane >> 2;
        const int fc = 2 * (lane & 3);
#pragma unroll
        for (int mi = 0; mi < 2; mi++)
#pragma unroll
            for (int nt = 0; nt < 4; nt++) {
                float* a = acc[mi * 4 + nt];
                int r = mi * 16 + fr;
                int c = nt * 8 + fc;
                atomicAdd(&gc[r * 33 + c],           a[0]);
                atomicAdd(&gc[r * 33 + c + 1],       a[1]);
                atomicAdd(&gc[(r + 8) * 33 + c],     a[2]);
                atomicAdd(&gc[(r + 8) * 33 + c + 1], a[3]);
            }
        atomicAdd(&rs[row], rsum);
    }
    __syncthreads();

    for (int i = tid; i < 1024; i += NTHR)
        atomicAdd(&g_gram[pair][i >> 5][i & 31], (double)gc[(i >> 5) * 33 + (i & 31)]);
    if (tid < 32)
        atomicAdd(&g_sums[pair][tid], (double)rs[tid]);
}

// ---------------------------------------------------------------------------
// Sinkhorn solver: 3 blocks (one per pair), 1024 threads = 4 softmins x 16x16.
// ---------------------------------------------------------------------------
__global__ void __launch_bounds__(1024, 1)
solver_kernel(float* out)
{
    const int p = blockIdx.x;
    __shared__ float Cxy[16][16], Cxx[16][16], Cyy[16][16];
    __shared__ float pot[2][4][16];
    __shared__ float fin[4][16];
    __shared__ float epss[60];
    __shared__ double Ssh[32];

    const int tid = threadIdx.x;
    const int q = tid >> 8;
    const int i = (tid >> 4) & 15;
    const int j = tid & 15;

    if (tid < 32) Ssh[tid] = g_sums[p][tid];
    if (tid < 60) {
        double e = pow(0.9025, (double)tid);
        epss[tid] = (float)fmax(e, 0.0025);
    }
    if (tid < 64) pot[0][tid >> 4][tid & 15] = 0.f;
    __syncthreads();

    if (tid < 256) {
        int ii = tid >> 4, jj = tid & 15;
        double Si  = Ssh[ii],      Sj  = Ssh[jj];
        double Syi = Ssh[16 + ii], Syj = Ssh[16 + jj];
        double a2i = g_gram[p][ii][ii] / (Si * Si);
        double a2j = g_gram[p][jj][jj] / (Sj * Sj);
        double b2i = g_gram[p][16 + ii][16 + ii] / (Syi * Syi);
        double b2j = g_gram[p][16 + jj][16 + jj] / (Syj * Syj);
        double dxy = g_gram[p][ii][16 + jj] / (Si * Syj);
        int lo = min(ii, jj), hi = max(ii, jj);
        double dxx = g_gram[p][lo][hi]           / (Si * Sj);
        double dyy = g_gram[p][16 + lo][16 + hi] / (Syi * Syj);
        Cxy[ii][jj] = (float)(0.5 * (a2i + b2j) - dxy);
        Cxx[ii][jj] = (float)(0.5 * (a2i + a2j) - dxx);
        Cyy[ii][jj] = (float)(0.5 * (b2i + b2j) - dyy);
    }
    __syncthreads();

    int cur = 0;
    for (int s = 0; s < 60; s++) {
        float eps = epss[s];
        float inv_eps = 1.0f / eps;
        float h, Cv, old;
        if (q == 0)      { h = pot[cur][1][j]; Cv = Cxy[i][j]; old = pot[cur][0][i]; }
        else if (q == 1) { h = pot[cur][0][j]; Cv = Cxy[j][i]; old = pot[cur][1][i]; }
        else if (q == 2) { h = pot[cur][2][j]; Cv = Cxx[i][j]; old = pot[cur][2][i]; }
        else             { h = pot[cur][3][j]; Cv = Cyy[i][j]; old = pot[cur][3][i]; }
        float u = (h - Cv) * inv_eps;
        float t = u * fmaf(u, fmaf(u, 0.16666667f, 0.5f), 1.0f);   // expm1
        t += __shfl_xor_sync(0xffffffffu, t, 1);
        t += __shfl_xor_sync(0xffffffffu, t, 2);
        t += __shfl_xor_sync(0xffffffffu, t, 4);
        t += __shfl_xor_sync(0xffffffffu, t, 8);
        if (j == 0) {
            float m = t * 0.0625f;
            float l = m * fmaf(m, fmaf(m, 0.33333333f, -0.5f), 1.0f);  // log1p
            pot[cur ^ 1][q][i] = 0.5f * (old - eps * l);
        }
        __syncthreads();
        cur ^= 1;
    }

    {
        const float eps = 0.0025f;
        const float inv_eps = 1.0f / eps;
        float h, Cv;
        if (q == 0)      { h = pot[cur][1][j]; Cv = Cxy[i][j]; }
        else if (q == 1) { h = pot[cur][0][j]; Cv = Cxy[j][i]; }
        else if (q == 2) { h = pot[cur][2][j]; Cv = Cxx[i][j]; }
        else             { h = pot[cur][3][j]; Cv = Cyy[i][j]; }
        float u = (h - Cv) * inv_eps;
        float t = u * fmaf(u, fmaf(u, 0.16666667f, 0.5f), 1.0f);
        t += __shfl_xor_sync(0xffffffffu, t, 1);
        t += __shfl_xor_sync(0xffffffffu, t, 2);
        t += __shfl_xor_sync(0xffffffffu, t, 4);
        t += __shfl_xor_sync(0xffffffffu, t, 8);
        if (j == 0) {
            float m = t * 0.0625f;
            float l = m * fmaf(m, fmaf(m, 0.33333333f, -0.5f), 1.0f);
            fin[q][i] = -eps * l;
        }
        __syncthreads();
    }

    if (tid == 0) {
        double acc2 = 0.0;
        for (int ii = 0; ii < 16; ii++)
            acc2 += ((double)fin[0][ii] - (double)fin[2][ii])
                  + ((double)fin[1][ii] - (double)fin[3][ii]);
        atomicAdd(out, (float)(acc2 / 48.0));
    }
}

// ---------------------------------------------------------------------------
extern "C" void kernel_launch(void* const* d_in, const int* in_sizes, int n_in,
                              void* d_out, int out_size)
{
    (void)out_size;
    // Pair the 6 inputs by element count (divergence is symmetric in (x, y)).
    int idx[6] = {0, 1, 2, 3, 4, 5};
    int n = (n_in < 6) ? n_in : 6;
    for (int a = 0; a < n; a++)
        for (int b = a + 1; b < n; b++)
            if (in_sizes[idx[b]] > in_sizes[idx[a]]) {
                int tmp = idx[a]; idx[a] = idx[b]; idx[b] = tmp;
            }

    const float* T[3]; const float* R[3]; int M[3]; int nb[3];
    for (int p = 0; p < 3; p++) {
        T[p] = (const float*)d_in[idx[2 * p]];
        R[p] = (const float*)d_in[idx[2 * p + 1]];
        M[p] = in_sizes[idx[2 * p]] / BROWS;
        int iters = M[p] >> 8;                 // TKI = 256
        nb[p] = (iters + 48) / 49;             // ~one wave over 147 blocks
        if (nb[p] < 1) nb[p] = 1;
        if (nb[p] > iters) nb[p] = iters;
    }

    zero_kernel<<<1, 256>>>((float*)d_out);
    gram_kernel<<<nb[0] + nb[1] + nb[2], NTHR>>>(
        T[0], R[0], M[0], nb[0],
        T[1], R[1], M[1], nb[1],
        T[2], R[2], M[2], nb[2]);
    solver_kernel<<<3, 1024>>>((float*)d_out);
}